// round 11
// baseline (speedup 1.0000x reference)
#include <cuda_runtime.h>
#include <math.h>

// Fixed problem shape (ReRanker reference): B=256, C=128, D=1024, fp32.
#define BB 256
#define CC 128
#define DD 1024
#define NQ 4                 // quarter-batch tasks
#define RQ 32                // rows per task
#define RPW 4                // rows per warp
#define NW 8                 // 256 threads, 8 warps
#define GRID 256             // persistent CTAs, all co-resident; 1024/256 = 4 exact
#define NTASK (BB * NQ)      // 1024 tasks
#define EPS 1e-8f
#define EPS2 1e-16f

// Scratch (device globals — no runtime allocation).
__device__ float g_Spart[BB][NQ][DD];   // 4 MB quarter partial S
__device__ float g_scpart[BB][NQ];      // partials of sum_c (summ·cand_c)/cn_c
__device__ int   g_flag[BB];            // quarters-done counter

__global__ void k_init_flags() {
    int i = blockIdx.x * blockDim.x + threadIdx.x;
    if (i < BB) g_flag[i] = 0;
}

struct F8 { float4 lo, hi; };

__device__ __forceinline__ F8 unpack(unsigned long long u0, unsigned long long u1,
                                     unsigned long long u2, unsigned long long u3) {
    F8 v;
    v.lo.x = __uint_as_float((unsigned)u0); v.lo.y = __uint_as_float((unsigned)(u0 >> 32));
    v.lo.z = __uint_as_float((unsigned)u1); v.lo.w = __uint_as_float((unsigned)(u1 >> 32));
    v.hi.x = __uint_as_float((unsigned)u2); v.hi.y = __uint_as_float((unsigned)(u2 >> 32));
    v.hi.z = __uint_as_float((unsigned)u3); v.hi.w = __uint_as_float((unsigned)(u3 >> 32));
    return v;
}
__device__ __forceinline__ F8 ldg_evict_last(const float* p) {
    unsigned long long u0, u1, u2, u3;
    asm volatile("ld.global.nc.L2::evict_last.v4.b64 {%0,%1,%2,%3}, [%4];"
                 : "=l"(u0), "=l"(u1), "=l"(u2), "=l"(u3) : "l"(p));
    return unpack(u0, u1, u2, u3);
}
__device__ __forceinline__ F8 ldg_evict_first(const float* p) {
    unsigned long long u0, u1, u2, u3;
    asm volatile("ld.global.nc.L2::evict_first.v4.b64 {%0,%1,%2,%3}, [%4];"
                 : "=l"(u0), "=l"(u1), "=l"(u2), "=l"(u3) : "l"(p));
    return unpack(u0, u1, u2, u3);
}

__global__ void __launch_bounds__(256, 2) k_fused(
    const float* __restrict__ doc,
    const float* __restrict__ summ,
    const float* __restrict__ cand,
    float* __restrict__ out)
{
    // lo/hi split arrays: every LDS.128 below has 16B lane stride (conflict-free)
    __shared__ float4 docsA[128], docsB[128];    // 4 KB
    __shared__ float4 sumsA[128], sumsB[128];    // 4 KB
    __shared__ float4 SsmA[128],  SsmB[128];     // 4 KB
    __shared__ float4 swpA[NW][128];             // 16 KB
    __shared__ float4 swpB[NW][128];             // 16 KB
    __shared__ float  rcn_s[2][RQ];
    __shared__ float  red[3][NW];
    __shared__ float  wsum[NW];
    __shared__ float  rsn_s[2];
    __shared__ float  sc_rdn;

    const int tid = threadIdx.x;
    const int w   = tid >> 5;
    const int l   = tid & 31;

    int prev_t = -1;
    int buf = 0;

    for (int t = blockIdx.x; t < NTASK; t += GRID) {
        const int b    = t >> 2;
        const int q    = t & 3;
        const int row0 = q * RQ;

        // ---------- phase 0: doc/summary norms + doc·summary ----------
        {
            const float4* docg = (const float4*)(doc  + (size_t)b * DD);
            const float4* sumg = (const float4*)(summ + (size_t)b * DD);
            float4 dv = __ldg(docg + tid);
            float4 sv = __ldg(sumg + tid);
            if (tid & 1) { docsB[tid >> 1] = dv; sumsB[tid >> 1] = sv; }
            else         { docsA[tid >> 1] = dv; sumsA[tid >> 1] = sv; }
            float pdd = dv.x*dv.x + dv.y*dv.y + dv.z*dv.z + dv.w*dv.w;
            float pss = sv.x*sv.x + sv.y*sv.y + sv.z*sv.z + sv.w*sv.w;
            float pds = dv.x*sv.x + dv.y*sv.y + dv.z*sv.z + dv.w*sv.w;
            #pragma unroll
            for (int o = 16; o; o >>= 1) {
                pdd += __shfl_xor_sync(0xffffffffu, pdd, o);
                pss += __shfl_xor_sync(0xffffffffu, pss, o);
                pds += __shfl_xor_sync(0xffffffffu, pds, o);
            }
            if (l == 0) { red[0][w] = pdd; red[1][w] = pss; red[2][w] = pds; }
        }
        __syncthreads();
        if (tid == 0) {
            float dd = 0.f, ss = 0.f, ds = 0.f;
            #pragma unroll
            for (int i = 0; i < NW; i++) { dd += red[0][i]; ss += red[1][i]; ds += red[2][i]; }
            float dn = fmaxf(sqrtf(dd), EPS);
            float sn = fmaxf(sqrtf(ss), EPS);
            sc_rdn = 1.0f / dn;
            rsn_s[buf] = 1.0f / sn;
            if (q == 0)
                out[2 * BB * CC + b] = ds / (dn * sn);      // summary_score[b]
        }

        // ---------- prepare pass B of prev task: wait + build Ssm ----------
        const int  pb    = prev_t >> 2;
        const int  pq    = prev_t & 3;
        const int  prow0 = pq * RQ;
        const int  pbuf  = buf ^ 1;
        const bool hasB  = (prev_t >= 0);
        if (hasB) {
            if (tid == 0) {
                while (atomicAdd(&g_flag[pb], 0) < NQ) { }   // partners published last iter
                __threadfence();                              // acquire
            }
            __syncthreads();
            {
                float4 a = ((const float4*)g_Spart[pb][0])[tid];
                #pragma unroll
                for (int qq = 1; qq < NQ; qq++) {
                    float4 v = ((const float4*)g_Spart[pb][qq])[tid];
                    a.x += v.x; a.y += v.y; a.z += v.z; a.w += v.w;
                }
                if (tid & 1) SsmB[tid >> 1] = a; else SsmA[tid >> 1] = a;
            }
            if (pq == 0 && tid == 0) {
                float acc = g_scpart[pb][0] + g_scpart[pb][1]
                          + g_scpart[pb][2] + g_scpart[pb][3];
                out[2 * BB * CC + BB + pb] = acc * rsn_s[pbuf] * (1.0f / CC); // summary_avg
            }
        }
        __syncthreads();
        const float rdn = sc_rdn;

        // ---------- fused loop: A-stream(t, DRAM) interleaved with B-stream(t-1, L2) ----------
        const float* cb  = cand + ((size_t)b * CC + row0) * DD;
        const float* pcb = hasB ? cand + ((size_t)pb * CC + prow0) * DD : cb;
        F8 Sacc[4];
        #pragma unroll
        for (int i = 0; i < 4; i++) {
            Sacc[i].lo = make_float4(0.f, 0.f, 0.f, 0.f);
            Sacc[i].hi = make_float4(0.f, 0.f, 0.f, 0.f);
        }
        float scpart = 0.f;

        #pragma unroll
        for (int j = 0; j < RPW; j++) {
            const int rl = w + j * NW;
            const float* arow = cb  + (size_t)rl * DD;
            const float* brow = pcb + (size_t)rl * DD;

            F8 vc[4];
            #pragma unroll
            for (int i = 0; i < 4; i++) vc[i] = ldg_evict_last(arow + (i * 32 + l) * 8);
            F8 pc[4];
            if (hasB) {
                #pragma unroll
                for (int i = 0; i < 4; i++) pc[i] = ldg_evict_first(brow + (i * 32 + l) * 8);
            }

            // ---- A compute: norms / doc / summary dots ----
            float ss0 = 0.f, ss1 = 0.f, dd0 = 0.f, dd1 = 0.f, sd0 = 0.f, sd1 = 0.f;
            #pragma unroll
            for (int i = 0; i < 4; i++) {
                const int c = i * 32 + l;
                float4 a  = vc[i].lo;
                float4 d4 = docsA[c];
                float4 s4 = sumsA[c];
                ss0 = fmaf(a.x, a.x, ss0); ss0 = fmaf(a.y, a.y, ss0);
                ss0 = fmaf(a.z, a.z, ss0); ss0 = fmaf(a.w, a.w, ss0);
                dd0 = fmaf(a.x, d4.x, dd0); dd0 = fmaf(a.y, d4.y, dd0);
                dd0 = fmaf(a.z, d4.z, dd0); dd0 = fmaf(a.w, d4.w, dd0);
                sd0 = fmaf(a.x, s4.x, sd0); sd0 = fmaf(a.y, s4.y, sd0);
                sd0 = fmaf(a.z, s4.z, sd0); sd0 = fmaf(a.w, s4.w, sd0);
                float4 a1  = vc[i].hi;
                float4 d41 = docsB[c];
                float4 s41 = sumsB[c];
                ss1 = fmaf(a1.x, a1.x, ss1); ss1 = fmaf(a1.y, a1.y, ss1);
                ss1 = fmaf(a1.z, a1.z, ss1); ss1 = fmaf(a1.w, a1.w, ss1);
                dd1 = fmaf(a1.x, d41.x, dd1); dd1 = fmaf(a1.y, d41.y, dd1);
                dd1 = fmaf(a1.z, d41.z, dd1); dd1 = fmaf(a1.w, d41.w, dd1);
                sd1 = fmaf(a1.x, s41.x, sd1); sd1 = fmaf(a1.y, s41.y, sd1);
                sd1 = fmaf(a1.z, s41.z, sd1); sd1 = fmaf(a1.w, s41.w, sd1);
            }
            float ss = ss0 + ss1, dd = dd0 + dd1, sd = sd0 + sd1;
            #pragma unroll
            for (int o = 16; o; o >>= 1) {
                ss += __shfl_xor_sync(0xffffffffu, ss, o);
                dd += __shfl_xor_sync(0xffffffffu, dd, o);
                sd += __shfl_xor_sync(0xffffffffu, sd, o);
            }
            float rcn = rsqrtf(fmaxf(ss, EPS2));
            if (l == 0) {
                out[b * CC + row0 + rl] = dd * rcn * rdn;   // outer_score
                rcn_s[buf][rl] = rcn;
            }
            scpart = fmaf(sd, rcn, scpart);
            #pragma unroll
            for (int i = 0; i < 4; i++) {
                Sacc[i].lo.x = fmaf(vc[i].lo.x, rcn, Sacc[i].lo.x);
                Sacc[i].lo.y = fmaf(vc[i].lo.y, rcn, Sacc[i].lo.y);
                Sacc[i].lo.z = fmaf(vc[i].lo.z, rcn, Sacc[i].lo.z);
                Sacc[i].lo.w = fmaf(vc[i].lo.w, rcn, Sacc[i].lo.w);
                Sacc[i].hi.x = fmaf(vc[i].hi.x, rcn, Sacc[i].hi.x);
                Sacc[i].hi.y = fmaf(vc[i].hi.y, rcn, Sacc[i].hi.y);
                Sacc[i].hi.z = fmaf(vc[i].hi.z, rcn, Sacc[i].hi.z);
                Sacc[i].hi.w = fmaf(vc[i].hi.w, rcn, Sacc[i].hi.w);
            }

            // ---- B compute: inner score for prev task's row rl ----
            if (hasB) {
                float dot0 = 0.f, dot1 = 0.f;
                #pragma unroll
                for (int i = 0; i < 4; i++) {
                    const int c = i * 32 + l;
                    float4 a = pc[i].lo;
                    float4 s = SsmA[c];
                    dot0 = fmaf(a.x, s.x, dot0); dot0 = fmaf(a.y, s.y, dot0);
                    dot0 = fmaf(a.z, s.z, dot0); dot0 = fmaf(a.w, s.w, dot0);
                    float4 a1 = pc[i].hi;
                    float4 s1 = SsmB[c];
                    dot1 = fmaf(a1.x, s1.x, dot1); dot1 = fmaf(a1.y, s1.y, dot1);
                    dot1 = fmaf(a1.z, s1.z, dot1); dot1 = fmaf(a1.w, s1.w, dot1);
                }
                float dot = dot0 + dot1;
                #pragma unroll
                for (int o = 16; o; o >>= 1)
                    dot += __shfl_xor_sync(0xffffffffu, dot, o);
                if (l == 0) {
                    // chat_r · S includes the self term (==1 up to fp32 rounding)
                    out[BB * CC + pb * CC + prow0 + rl] =
                        (dot * rcn_s[pbuf][rl] - 1.0f) * (1.0f / (CC - 1));
                }
            }
        }

        // ---------- fold warp partials; publish quarter-S; signal ----------
        #pragma unroll
        for (int i = 0; i < 4; i++) {
            const int c = i * 32 + l;
            swpA[w][c] = Sacc[i].lo;
            swpB[w][c] = Sacc[i].hi;
        }
        if (l == 0) wsum[w] = scpart;
        __syncthreads();
        {
            const int c = tid >> 1;
            float4 st = (tid & 1) ? swpB[0][c] : swpA[0][c];
            #pragma unroll
            for (int ww = 1; ww < NW; ww++) {
                float4 v = (tid & 1) ? swpB[ww][c] : swpA[ww][c];
                st.x += v.x; st.y += v.y; st.z += v.z; st.w += v.w;
            }
            ((float4*)g_Spart[b][q])[tid] = st;
        }
        if (tid == 0) {
            float acc = 0.f;
            #pragma unroll
            for (int i = 0; i < NW; i++) acc += wsum[i];
            g_scpart[b][q] = acc;
        }
        __syncthreads();
        if (tid == 0) {
            __threadfence();                  // release Spart/scpart
            atomicAdd(&g_flag[b], 1);
        }
        __syncthreads();

        prev_t = t;
        buf ^= 1;
    }

    // ---------- epilogue: pass B for the final task ----------
    {
        const int pb    = prev_t >> 2;
        const int pq    = prev_t & 3;
        const int prow0 = pq * RQ;
        const int pbuf  = buf ^ 1;

        if (tid == 0) {
            while (atomicAdd(&g_flag[pb], 0) < NQ) { }
            __threadfence();
        }
        __syncthreads();
        {
            float4 a = ((const float4*)g_Spart[pb][0])[tid];
            #pragma unroll
            for (int qq = 1; qq < NQ; qq++) {
                float4 v = ((const float4*)g_Spart[pb][qq])[tid];
                a.x += v.x; a.y += v.y; a.z += v.z; a.w += v.w;
            }
            if (tid & 1) SsmB[tid >> 1] = a; else SsmA[tid >> 1] = a;
        }
        if (pq == 0 && tid == 0) {
            float acc = g_scpart[pb][0] + g_scpart[pb][1]
                      + g_scpart[pb][2] + g_scpart[pb][3];
            out[2 * BB * CC + BB + pb] = acc * rsn_s[pbuf] * (1.0f / CC);
        }
        __syncthreads();

        const float* pcb = cand + ((size_t)pb * CC + prow0) * DD;
        #pragma unroll
        for (int j = 0; j < RPW; j++) {
            const int rl = w + j * NW;
            const float* brow = pcb + (size_t)rl * DD;
            F8 pc[4];
            #pragma unroll
            for (int i = 0; i < 4; i++) pc[i] = ldg_evict_first(brow + (i * 32 + l) * 8);
            float dot0 = 0.f, dot1 = 0.f;
            #pragma unroll
            for (int i = 0; i < 4; i++) {
                const int c = i * 32 + l;
                float4 a = pc[i].lo;
                float4 s = SsmA[c];
                dot0 = fmaf(a.x, s.x, dot0); dot0 = fmaf(a.y, s.y, dot0);
                dot0 = fmaf(a.z, s.z, dot0); dot0 = fmaf(a.w, s.w, dot0);
                float4 a1 = pc[i].hi;
                float4 s1 = SsmB[c];
                dot1 = fmaf(a1.x, s1.x, dot1); dot1 = fmaf(a1.y, s1.y, dot1);
                dot1 = fmaf(a1.z, s1.z, dot1); dot1 = fmaf(a1.w, s1.w, dot1);
            }
            float dot = dot0 + dot1;
            #pragma unroll
            for (int o = 16; o; o >>= 1)
                dot += __shfl_xor_sync(0xffffffffu, dot, o);
            if (l == 0) {
                out[BB * CC + pb * CC + prow0 + rl] =
                    (dot * rcn_s[pbuf][rl] - 1.0f) * (1.0f / (CC - 1));
            }
        }
    }
}

extern "C" void kernel_launch(void* const* d_in, const int* in_sizes, int n_in,
                              void* d_out, int out_size) {
    const float* doc  = (const float*)d_in[0];   // [B, D]
    const float* summ = (const float*)d_in[1];   // [B, D]
    const float* cand = (const float*)d_in[2];   // [B, C, D]
    float* out = (float*)d_out;                  // [B*C | B*C | B | B]
    (void)in_sizes; (void)n_in; (void)out_size;

    k_init_flags<<<1, BB>>>();
    k_fused<<<GRID, 256>>>(doc, summ, cand, out);
}

// round 12
// speedup vs baseline: 1.3117x; 1.3117x over previous
#include <cuda_runtime.h>
#include <math.h>

// Fixed problem shape (ReRanker reference): B=256, C=128, D=1024, fp32.
#define BB 256
#define CC 128
#define DD 1024
#define HR 64                // rows per task (half batch)
#define NW 8                 // 256 threads, 8 warps
#define RPW 8                // rows per warp
#define GRID 296             // persistent CTAs, 2/SM, all co-resident
#define NTASK (BB * 2)       // 512 tasks
#define EPS 1e-8f
#define EPS2 1e-16f

// Scratch (device globals — no runtime allocation).
__device__ float g_Spart[BB][2][DD];    // 2 MB half-batch partial S
__device__ float g_scpart[BB][2];       // partial of sum_c (summ·cand_c)/cn_c
__device__ int   g_flag[BB];            // halves-done counter per batch
__device__ int   g_qhead;               // work-queue ticket counter

__global__ void k_init() {
    int i = blockIdx.x * blockDim.x + threadIdx.x;
    if (i < BB) g_flag[i] = 0;
    if (i == 0) g_qhead = 0;
}

struct F8 { float4 lo, hi; };

__device__ __forceinline__ F8 unpack(unsigned long long u0, unsigned long long u1,
                                     unsigned long long u2, unsigned long long u3) {
    F8 v;
    v.lo.x = __uint_as_float((unsigned)u0); v.lo.y = __uint_as_float((unsigned)(u0 >> 32));
    v.lo.z = __uint_as_float((unsigned)u1); v.lo.w = __uint_as_float((unsigned)(u1 >> 32));
    v.hi.x = __uint_as_float((unsigned)u2); v.hi.y = __uint_as_float((unsigned)(u2 >> 32));
    v.hi.z = __uint_as_float((unsigned)u3); v.hi.w = __uint_as_float((unsigned)(u3 >> 32));
    return v;
}
__device__ __forceinline__ F8 ldg_evict_last(const float* p) {
    unsigned long long u0, u1, u2, u3;
    asm volatile("ld.global.nc.L2::evict_last.v4.b64 {%0,%1,%2,%3}, [%4];"
                 : "=l"(u0), "=l"(u1), "=l"(u2), "=l"(u3) : "l"(p));
    return unpack(u0, u1, u2, u3);
}
__device__ __forceinline__ F8 ldg_evict_first(const float* p) {
    unsigned long long u0, u1, u2, u3;
    asm volatile("ld.global.nc.L2::evict_first.v4.b64 {%0,%1,%2,%3}, [%4];"
                 : "=l"(u0), "=l"(u1), "=l"(u2), "=l"(u3) : "l"(p));
    return unpack(u0, u1, u2, u3);
}

__global__ void __launch_bounds__(256, 2) k_fused(
    const float* __restrict__ doc,
    const float* __restrict__ summ,
    const float* __restrict__ cand,
    float* __restrict__ out)
{
    // lo/hi split: every hot LDS.128 has 16B lane stride (conflict-free)
    __shared__ float4 docsLo[128], docsHi[128];   // 4 KB
    __shared__ float4 sumsLo[128], sumsHi[128];   // 4 KB
    __shared__ float4 SsmLo[128],  SsmHi[128];    // 4 KB
    __shared__ float4 swpLo[NW][128];             // 16 KB
    __shared__ float4 swpHi[NW][128];             // 16 KB
    __shared__ float  rcn_s[HR];
    __shared__ float  red[3][NW];
    __shared__ float  wsum[NW];
    __shared__ float  sc_rdn, sc_rsn;
    __shared__ int    tsh;

    const int tid = threadIdx.x;
    const int w   = tid >> 5;
    const int l   = tid & 31;

    for (;;) {
        if (tid == 0) tsh = atomicAdd(&g_qhead, 1);
        __syncthreads();                 // broadcast ticket; also fences prev iter's smem reads
        const int t = tsh;
        if (t >= NTASK) break;

        const int b    = t >> 1;
        const int half = t & 1;
        const int row0 = half * HR;

        // ---------- phase 0: doc/summary norms + doc·summary ----------
        {
            const float4* docg = (const float4*)(doc  + (size_t)b * DD);
            const float4* sumg = (const float4*)(summ + (size_t)b * DD);
            float4 dv = __ldg(docg + tid);
            float4 sv = __ldg(sumg + tid);
            if (tid & 1) { docsHi[tid >> 1] = dv; sumsHi[tid >> 1] = sv; }
            else         { docsLo[tid >> 1] = dv; sumsLo[tid >> 1] = sv; }
            float pdd = dv.x*dv.x + dv.y*dv.y + dv.z*dv.z + dv.w*dv.w;
            float pss = sv.x*sv.x + sv.y*sv.y + sv.z*sv.z + sv.w*sv.w;
            float pds = dv.x*sv.x + dv.y*sv.y + dv.z*sv.z + dv.w*sv.w;
            #pragma unroll
            for (int o = 16; o; o >>= 1) {
                pdd += __shfl_xor_sync(0xffffffffu, pdd, o);
                pss += __shfl_xor_sync(0xffffffffu, pss, o);
                pds += __shfl_xor_sync(0xffffffffu, pds, o);
            }
            if (l == 0) { red[0][w] = pdd; red[1][w] = pss; red[2][w] = pds; }
        }
        __syncthreads();
        if (tid == 0) {
            float dd = 0.f, ss = 0.f, ds = 0.f;
            #pragma unroll
            for (int i = 0; i < NW; i++) { dd += red[0][i]; ss += red[1][i]; ds += red[2][i]; }
            float dn = fmaxf(sqrtf(dd), EPS);
            float sn = fmaxf(sqrtf(ss), EPS);
            sc_rdn = 1.0f / dn;
            sc_rsn = 1.0f / sn;
            if (half == 0)
                out[2 * BB * CC + b] = ds / (dn * sn);      // summary_score[b]
        }
        __syncthreads();
        const float rdn = sc_rdn;

        // ---------- pass A: stream 64 rows (evict_last pins in L2) ----------
        const float* cb = cand + ((size_t)b * CC + row0) * DD;
        F8 Sacc[4];
        #pragma unroll
        for (int i = 0; i < 4; i++) {
            Sacc[i].lo = make_float4(0.f, 0.f, 0.f, 0.f);
            Sacc[i].hi = make_float4(0.f, 0.f, 0.f, 0.f);
        }
        float scpart = 0.f;

        F8 vc[4];
        {
            const float* rowp = cb + (size_t)w * DD;
            #pragma unroll
            for (int i = 0; i < 4; i++) vc[i] = ldg_evict_last(rowp + (i * 32 + l) * 8);
        }
        #pragma unroll
        for (int j = 0; j < RPW; j++) {
            const int rl = w + j * NW;
            F8 vn[4];
            if (j + 1 < RPW) {
                const float* nrow = cb + (size_t)(rl + NW) * DD;
                #pragma unroll
                for (int i = 0; i < 4; i++) vn[i] = ldg_evict_last(nrow + (i * 32 + l) * 8);
            }
            float ss0 = 0.f, ss1 = 0.f, dd0 = 0.f, dd1 = 0.f, sd0 = 0.f, sd1 = 0.f;
            #pragma unroll
            for (int i = 0; i < 4; i++) {
                const int c = i * 32 + l;
                float4 a  = vc[i].lo;
                float4 d4 = docsLo[c];
                float4 s4 = sumsLo[c];
                ss0 = fmaf(a.x, a.x, ss0); ss0 = fmaf(a.y, a.y, ss0);
                ss0 = fmaf(a.z, a.z, ss0); ss0 = fmaf(a.w, a.w, ss0);
                dd0 = fmaf(a.x, d4.x, dd0); dd0 = fmaf(a.y, d4.y, dd0);
                dd0 = fmaf(a.z, d4.z, dd0); dd0 = fmaf(a.w, d4.w, dd0);
                sd0 = fmaf(a.x, s4.x, sd0); sd0 = fmaf(a.y, s4.y, sd0);
                sd0 = fmaf(a.z, s4.z, sd0); sd0 = fmaf(a.w, s4.w, sd0);
                float4 a1  = vc[i].hi;
                float4 d41 = docsHi[c];
                float4 s41 = sumsHi[c];
                ss1 = fmaf(a1.x, a1.x, ss1); ss1 = fmaf(a1.y, a1.y, ss1);
                ss1 = fmaf(a1.z, a1.z, ss1); ss1 = fmaf(a1.w, a1.w, ss1);
                dd1 = fmaf(a1.x, d41.x, dd1); dd1 = fmaf(a1.y, d41.y, dd1);
                dd1 = fmaf(a1.z, d41.z, dd1); dd1 = fmaf(a1.w, d41.w, dd1);
                sd1 = fmaf(a1.x, s41.x, sd1); sd1 = fmaf(a1.y, s41.y, sd1);
                sd1 = fmaf(a1.w, s41.w, sd1); sd1 = fmaf(a1.z, s41.z, sd1);
            }
            float ss = ss0 + ss1, dd = dd0 + dd1, sd = sd0 + sd1;
            #pragma unroll
            for (int o = 16; o; o >>= 1) {
                ss += __shfl_xor_sync(0xffffffffu, ss, o);
                dd += __shfl_xor_sync(0xffffffffu, dd, o);
                sd += __shfl_xor_sync(0xffffffffu, sd, o);
            }
            float rcn = rsqrtf(fmaxf(ss, EPS2));
            if (l == 0) {
                out[b * CC + row0 + rl] = dd * rcn * rdn;   // outer_score
                rcn_s[rl] = rcn;
            }
            scpart = fmaf(sd, rcn, scpart);
            #pragma unroll
            for (int i = 0; i < 4; i++) {
                Sacc[i].lo.x = fmaf(vc[i].lo.x, rcn, Sacc[i].lo.x);
                Sacc[i].lo.y = fmaf(vc[i].lo.y, rcn, Sacc[i].lo.y);
                Sacc[i].lo.z = fmaf(vc[i].lo.z, rcn, Sacc[i].lo.z);
                Sacc[i].lo.w = fmaf(vc[i].lo.w, rcn, Sacc[i].lo.w);
                Sacc[i].hi.x = fmaf(vc[i].hi.x, rcn, Sacc[i].hi.x);
                Sacc[i].hi.y = fmaf(vc[i].hi.y, rcn, Sacc[i].hi.y);
                Sacc[i].hi.z = fmaf(vc[i].hi.z, rcn, Sacc[i].hi.z);
                Sacc[i].hi.w = fmaf(vc[i].hi.w, rcn, Sacc[i].hi.w);
            }
            #pragma unroll
            for (int i = 0; i < 4; i++) vc[i] = vn[i];
        }

        // ---------- fold warp partials; publish half-S; signal ----------
        #pragma unroll
        for (int i = 0; i < 4; i++) {
            const int c = i * 32 + l;
            swpLo[w][c] = Sacc[i].lo;
            swpHi[w][c] = Sacc[i].hi;
        }
        if (l == 0) wsum[w] = scpart;
        __syncthreads();
        {
            const int c = tid >> 1;
            float4 st = (tid & 1) ? swpHi[0][c] : swpLo[0][c];
            #pragma unroll
            for (int ww = 1; ww < NW; ww++) {
                float4 v = (tid & 1) ? swpHi[ww][c] : swpLo[ww][c];
                st.x += v.x; st.y += v.y; st.z += v.z; st.w += v.w;
            }
            ((float4*)g_Spart[b][half])[tid] = st;
        }
        if (tid == 0) {
            float acc = 0.f;
            #pragma unroll
            for (int i = 0; i < NW; i++) acc += wsum[i];
            g_scpart[b][half] = acc;
        }
        __syncthreads();
        if (tid == 0) {
            __threadfence();                      // release
            atomicAdd(&g_flag[b], 1);
            while (atomicAdd(&g_flag[b], 0) < 2) { }   // wait for partner half
            __threadfence();                      // acquire
        }
        __syncthreads();

        // ---------- S = both halves; pass B re-reads own rows (L2 hits) ----------
        {
            const float4* s0 = (const float4*)g_Spart[b][0];
            const float4* s1 = (const float4*)g_Spart[b][1];
            float4 a = s0[tid];
            float4 c = s1[tid];
            a.x += c.x; a.y += c.y; a.z += c.z; a.w += c.w;
            if (tid & 1) SsmHi[tid >> 1] = a; else SsmLo[tid >> 1] = a;
        }
        if (half == 0 && tid == 0) {
            out[2 * BB * CC + BB + b] =
                (g_scpart[b][0] + g_scpart[b][1]) * sc_rsn * (1.0f / CC);  // summary_avg
        }
        __syncthreads();

        {
            F8 pc[4];
            const float* rowp = cb + (size_t)w * DD;
            #pragma unroll
            for (int i = 0; i < 4; i++) pc[i] = ldg_evict_first(rowp + (i * 32 + l) * 8);

            #pragma unroll
            for (int j = 0; j < RPW; j++) {
                const int rl = w + j * NW;
                F8 pn[4];
                if (j + 1 < RPW) {
                    const float* nrow = cb + (size_t)(rl + NW) * DD;
                    #pragma unroll
                    for (int i = 0; i < 4; i++) pn[i] = ldg_evict_first(nrow + (i * 32 + l) * 8);
                }
                float dot0 = 0.f, dot1 = 0.f;
                #pragma unroll
                for (int i = 0; i < 4; i++) {
                    const int c = i * 32 + l;
                    float4 a = pc[i].lo;
                    float4 s = SsmLo[c];
                    dot0 = fmaf(a.x, s.x, dot0); dot0 = fmaf(a.y, s.y, dot0);
                    dot0 = fmaf(a.z, s.z, dot0); dot0 = fmaf(a.w, s.w, dot0);
                    float4 a1 = pc[i].hi;
                    float4 s1 = SsmHi[c];
                    dot1 = fmaf(a1.x, s1.x, dot1); dot1 = fmaf(a1.y, s1.y, dot1);
                    dot1 = fmaf(a1.z, s1.z, dot1); dot1 = fmaf(a1.w, s1.w, dot1);
                }
                float dot = dot0 + dot1;
                #pragma unroll
                for (int o = 16; o; o >>= 1)
                    dot += __shfl_xor_sync(0xffffffffu, dot, o);
                if (l == 0) {
                    // chat_r · S includes the self term (==1 up to fp32 rounding)
                    out[BB * CC + b * CC + row0 + rl] =
                        (dot * rcn_s[rl] - 1.0f) * (1.0f / (CC - 1));
                }
                #pragma unroll
                for (int i = 0; i < 4; i++) pc[i] = pn[i];
            }
        }
        // loop-top __syncthreads() fences these smem reads vs next task's writes
    }
}

extern "C" void kernel_launch(void* const* d_in, const int* in_sizes, int n_in,
                              void* d_out, int out_size) {
    const float* doc  = (const float*)d_in[0];   // [B, D]
    const float* summ = (const float*)d_in[1];   // [B, D]
    const float* cand = (const float*)d_in[2];   // [B, C, D]
    float* out = (float*)d_out;                  // [B*C | B*C | B | B]
    (void)in_sizes; (void)n_in; (void)out_size;

    k_init<<<1, BB>>>();
    k_fused<<<GRID, 256>>>(doc, summ, cand, out);
}